// round 3
// baseline (speedup 1.0000x reference)
#include <cuda_runtime.h>
#include <cstdint>

// Depth-to-space r=4, x-major channel ordering:
//   out[b, c, y, x] = in[b, c*16 + 4*(x%4) + (y%4), y/4, x/4]
// in : (16, 4096, 32, 32) fp32  -> 256 MB
// out: (16, 256, 128, 128) fp32 -> 256 MB
//
// v8.f32 (32B) loads/stores, warp-contiguous reads:
//   tid bits: [xq:2][yblo:3][yr:2][ybhi:2][c:8][b:4]
// Within a warp, lanes vary over (xq, yblo) with yr fixed, so each of the 4
// ld.v8 instructions reads 32 lanes x 32B = 1KB fully contiguous from one
// input channel. Stores are 128B contiguous per thread (full lines).

__global__ void __launch_bounds__(256, 5) scale_transfer_v8c_kernel(
    const float* __restrict__ in, float* __restrict__ out)
{
    unsigned tid = blockIdx.x * blockDim.x + threadIdx.x;
    unsigned xq   = tid & 3;
    unsigned yblo = (tid >> 2) & 7;
    unsigned yr   = (tid >> 5) & 3;
    unsigned ybhi = (tid >> 7) & 3;
    unsigned c    = (tid >> 9) & 255;
    unsigned b    = tid >> 17;

    unsigned yb = ybhi * 8 + yblo;      // 0..31
    unsigned y  = yb * 4 + yr;          // 0..127

    // input float index; xr channel stride = 4 channels = 4096 floats (16KB)
    const float* p =
        in + (((b * 4096u + c * 16u + yr) * 32u + yb) * 32u + xq * 8u);

    float r[4][8];
#pragma unroll
    for (int xr = 0; xr < 4; xr++) {
        const float* q = p + xr * 4096;
        asm volatile(
            "ld.global.nc.L2::evict_first.v8.f32 "
            "{%0,%1,%2,%3,%4,%5,%6,%7}, [%8];"
            : "=f"(r[xr][0]), "=f"(r[xr][1]), "=f"(r[xr][2]), "=f"(r[xr][3]),
              "=f"(r[xr][4]), "=f"(r[xr][5]), "=f"(r[xr][6]), "=f"(r[xr][7])
            : "l"(q));
    }

    // output: 32 consecutive floats (x = xq*32 .. xq*32+31) of row (b,c,y)
    float* o = out + (((b * 256u + c) * 128u + y) * 128u + xq * 32u);

#pragma unroll
    for (int j = 0; j < 4; j++) {
        int i0 = 2 * j, i1 = 2 * j + 1;
        asm volatile(
            "st.global.L2::evict_first.v8.f32 "
            "[%0], {%1,%2,%3,%4,%5,%6,%7,%8};"
            :
            : "l"(o + j * 8),
              "f"(r[0][i0]), "f"(r[1][i0]), "f"(r[2][i0]), "f"(r[3][i0]),
              "f"(r[0][i1]), "f"(r[1][i1]), "f"(r[2][i1]), "f"(r[3][i1])
            : "memory");
    }
}

extern "C" void kernel_launch(void* const* d_in, const int* in_sizes, int n_in,
                              void* d_out, int out_size)
{
    const float* in = (const float*)d_in[0];
    float* out = (float*)d_out;

    const int total_threads = 16 * 256 * 128 * 4;  // 2,097,152
    const int block = 256;
    const int grid = total_threads / block;        // 8192

    scale_transfer_v8c_kernel<<<grid, block>>>(in, out);
}

// round 4
// speedup vs baseline: 1.0255x; 1.0255x over previous
#include <cuda_runtime.h>
#include <cstdint>

// Depth-to-space r=4, x-major channel ordering:
//   out[b, c, y, x] = in[b, c*16 + 4*(x%4) + (y%4), y/4, x/4]
// in : (16, 4096, 32, 32) fp32  -> 256 MB
// out: (16, 256, 128, 128) fp32 -> 256 MB
//
// Round-2 mapping (proven best: warp covers 8 consecutive output rows dense),
// with 2x work per thread (rows y and y+64) for doubled load MLP.
// All accesses are 32B v8.f32 (full sectors).

__global__ void __launch_bounds__(256) scale_transfer_v8x2_kernel(
    const float* __restrict__ in, float* __restrict__ out)
{
    unsigned tid = blockIdx.x * blockDim.x + threadIdx.x;
    // tid layout: b[4] c[8] ylo[6] xq[2]  -> 16*256*64*4 = 1,048,576 threads
    unsigned xq  = tid & 3;            // 8-float group within 32-float input row
    unsigned ylo = (tid >> 2) & 63;    // y in {ylo, ylo+64}
    unsigned c   = (tid >> 8) & 255;
    unsigned b   = tid >> 16;

    unsigned yr = ylo & 3;             // same for ylo and ylo+64
    unsigned yb0 = ylo >> 2;           // 0..15
    unsigned yb1 = yb0 + 16;           // for y+64

    // input float index; xr channel stride = 4 channels = 4096 floats
    const float* p0 =
        in + (((b * 4096u + c * 16u + yr) * 32u + yb0) * 32u + xq * 8u);
    const float* p1 = p0 + 16u * 32u;  // yb1 = yb0 + 16

    float r[2][4][8];
#pragma unroll
    for (int xr = 0; xr < 4; xr++) {
        const float* q = p0 + xr * 4096;
        asm volatile(
            "ld.global.nc.v8.f32 {%0,%1,%2,%3,%4,%5,%6,%7}, [%8];"
            : "=f"(r[0][xr][0]), "=f"(r[0][xr][1]), "=f"(r[0][xr][2]), "=f"(r[0][xr][3]),
              "=f"(r[0][xr][4]), "=f"(r[0][xr][5]), "=f"(r[0][xr][6]), "=f"(r[0][xr][7])
            : "l"(q));
    }
#pragma unroll
    for (int xr = 0; xr < 4; xr++) {
        const float* q = p1 + xr * 4096;
        asm volatile(
            "ld.global.nc.v8.f32 {%0,%1,%2,%3,%4,%5,%6,%7}, [%8];"
            : "=f"(r[1][xr][0]), "=f"(r[1][xr][1]), "=f"(r[1][xr][2]), "=f"(r[1][xr][3]),
              "=f"(r[1][xr][4]), "=f"(r[1][xr][5]), "=f"(r[1][xr][6]), "=f"(r[1][xr][7])
            : "l"(q));
    }

    // output: 32 consecutive floats (x = xq*32..xq*32+31) of rows y and y+64
    float* o0 = out + (((b * 256u + c) * 128u + ylo) * 128u + xq * 32u);
    float* o1 = o0 + 64u * 128u;

#pragma unroll
    for (int g = 0; g < 2; g++) {
        float* o = g ? o1 : o0;
#pragma unroll
        for (int j = 0; j < 4; j++) {
            int i0 = 2 * j, i1 = 2 * j + 1;
            asm volatile(
                "st.global.v8.f32 [%0], {%1,%2,%3,%4,%5,%6,%7,%8};"
                :
                : "l"(o + j * 8),
                  "f"(r[g][0][i0]), "f"(r[g][1][i0]), "f"(r[g][2][i0]), "f"(r[g][3][i0]),
                  "f"(r[g][0][i1]), "f"(r[g][1][i1]), "f"(r[g][2][i1]), "f"(r[g][3][i1])
                : "memory");
        }
    }
}

extern "C" void kernel_launch(void* const* d_in, const int* in_sizes, int n_in,
                              void* d_out, int out_size)
{
    const float* in = (const float*)d_in[0];
    float* out = (float*)d_out;

    const int total_threads = 16 * 256 * 64 * 4;   // 1,048,576
    const int block = 256;
    const int grid = total_threads / block;        // 4096

    scale_transfer_v8x2_kernel<<<grid, block>>>(in, out);
}